// round 13
// baseline (speedup 1.0000x reference)
#include <cuda_runtime.h>
#include <cuda_bf16.h>
#include <cuda_fp16.h>
#include <math.h>

// ---------------------------------------------------------------------------
// Problem constants
// ---------------------------------------------------------------------------
#define T_TOK   6400
#define D_DIM   512
#define HID     1024
#define N_SEQ   2048
#define EPS     1e-6f
#define INV_N   (1.0f/2048.0f)

__device__ __constant__ int c_off[5] = {0, 2048, 3584, 4608, 6400};
__device__ __constant__ unsigned char c_ord[100][2] = {
 {0,31},{0,30},{0,29},{0,28},
 {0,27},{3,27},{0,26},{3,26},{0,25},{3,25},{0,24},{3,24},
 {0,23},{1,23},{3,23},{0,22},{1,22},{3,22},{0,21},{1,21},{3,21},
 {0,20},{1,20},{3,20},{0,19},{1,19},{3,19},{0,18},{1,18},{3,18},
 {0,17},{1,17},{3,17},{0,16},{1,16},{3,16},
 {0,15},{1,15},{2,15},{3,15},{0,14},{1,14},{2,14},{3,14},
 {0,13},{1,13},{2,13},{3,13},{0,12},{1,12},{2,12},{3,12},
 {0,11},{1,11},{2,11},{3,11},{0,10},{1,10},{2,10},{3,10},
 {0,9},{1,9},{2,9},{3,9},{0,8},{1,8},{2,8},{3,8},
 {0,7},{1,7},{2,7},{3,7},{0,6},{1,6},{2,6},{3,6},
 {0,5},{1,5},{2,5},{3,5},{0,4},{1,4},{2,4},{3,4},
 {0,3},{1,3},{2,3},{3,3},{0,2},{1,2},{2,2},{3,2},
 {0,1},{1,1},{2,1},{3,1},{0,0},{1,0},{2,0},{3,0}};

// ---------------------------------------------------------------------------
// Scratch
// ---------------------------------------------------------------------------
__device__ __half g_xnh [T_TOK * D_DIM];
__device__ __half g_wh  [D_DIM * HID];
__device__ __half g_owh [D_DIM * 256];
__device__ float  g_u   [T_TOK * 256];
__device__ __half g_qh  [T_TOK * 256];
__device__ __half g_kh  [T_TOK * 256];
__device__ __half g_vh  [T_TOK * 256];
__device__ float  g_attn[T_TOK * 256];
__device__ __half g_oinh[T_TOK * 256];

// ---------------------------------------------------------------------------
// helpers
// ---------------------------------------------------------------------------
__device__ __forceinline__ void mma16(float* c, const unsigned* a, unsigned b0, unsigned b1) {
    asm volatile(
      "mma.sync.aligned.m16n8k16.row.col.f32.f16.f16.f32 "
      "{%0,%1,%2,%3}, {%4,%5,%6,%7}, {%8,%9}, {%0,%1,%2,%3};"
      : "+f"(c[0]), "+f"(c[1]), "+f"(c[2]), "+f"(c[3])
      : "r"(a[0]), "r"(a[1]), "r"(a[2]), "r"(a[3]), "r"(b0), "r"(b1));
}
__device__ __forceinline__ void ldsm4(unsigned* r, unsigned addr) {
    asm volatile("ldmatrix.sync.aligned.m8n8.x4.shared.b16 {%0,%1,%2,%3}, [%4];"
        : "=r"(r[0]), "=r"(r[1]), "=r"(r[2]), "=r"(r[3]) : "r"(addr));
}
__device__ __forceinline__ void ldsm4t(unsigned* r, unsigned addr) {
    asm volatile("ldmatrix.sync.aligned.m8n8.x4.trans.shared.b16 {%0,%1,%2,%3}, [%4];"
        : "=r"(r[0]), "=r"(r[1]), "=r"(r[2]), "=r"(r[3]) : "r"(addr));
}
__device__ __forceinline__ void cpa16(unsigned saddr, const void* g) {
    asm volatile("cp.async.ca.shared.global [%0], [%1], 16;" :: "r"(saddr), "l"(g));
}
__device__ __forceinline__ unsigned packh2(float x, float y) {
    __half2 h = __floats2half2_rn(x, y);
    return *(unsigned*)&h;
}
__device__ __forceinline__ float silu_f(float s) {
    return s * __fdividef(1.0f, 1.0f + __expf(-s));
}
// silu on a float pair, computed in half2 (1 MUFU), returns packed half2 == pa frag
__device__ __forceinline__ unsigned silu2(float a, float b) {
    __half2 h05 = __floats2half2_rn(0.5f, 0.5f);
    __half2 s = __floats2half2_rn(a, b);
    __half2 arg = __hmul2(s, h05);
    unsigned t;
    asm("tanh.approx.f16x2 %0, %1;" : "=r"(t) : "r"(*(unsigned*)&arg));
    __half2 sig = __hfma2(*(__half2*)&t, h05, h05);
    __half2 p = __hmul2(s, sig);
    return *(unsigned*)&p;
}

// ---------------------------------------------------------------------------
// Kernel 0: one-shot fp16 conversion of uvqk and o_w
// ---------------------------------------------------------------------------
__global__ void convert_w_kernel(const float* __restrict__ uvqk,
                                 const float* __restrict__ ow) {
    int i = blockIdx.x * 1024 + threadIdx.x * 4;
    if (blockIdx.x < 512) {
        float4 v = *(const float4*)(uvqk + i);
        *(uint2*)&g_wh[i] = make_uint2(packh2(v.x, v.y), packh2(v.z, v.w));
    } else {
        int j = i - 512 * 1024;
        float4 v = *(const float4*)(ow + j);
        *(uint2*)&g_owh[j] = make_uint2(packh2(v.x, v.y), packh2(v.z, v.w));
    }
}

// ---------------------------------------------------------------------------
// Kernel 1: LayerNorm over D=512, warp-per-token, fp16 output
// ---------------------------------------------------------------------------
__global__ void ln_x_kernel(const float* __restrict__ x) {
    int t = blockIdx.x * 8 + (threadIdx.x >> 5);
    int lane = threadIdx.x & 31;
    const float* row = x + (size_t)t * D_DIM + lane * 4;
    float4 v[4];
    #pragma unroll
    for (int w = 0; w < 4; w++) v[w] = *(const float4*)(row + w * 128);
    float s = 0.f, q = 0.f;
    #pragma unroll
    for (int w = 0; w < 4; w++) {
        s += v[w].x + v[w].y + v[w].z + v[w].w;
        q += v[w].x*v[w].x + v[w].y*v[w].y + v[w].z*v[w].z + v[w].w*v[w].w;
    }
    #pragma unroll
    for (int o = 16; o > 0; o >>= 1) {
        s += __shfl_xor_sync(0xffffffffu, s, o);
        q += __shfl_xor_sync(0xffffffffu, q, o);
    }
    float m = s * (1.0f / D_DIM);
    float r = rsqrtf(q * (1.0f / D_DIM) - m * m + EPS);
    __half* dst = g_xnh + (size_t)t * D_DIM + lane * 4;
    #pragma unroll
    for (int w = 0; w < 4; w++) {
        *(uint2*)(dst + w * 128) = make_uint2(
            packh2((v[w].x - m) * r, (v[w].y - m) * r),
            packh2((v[w].z - m) * r, (v[w].w - m) * r));
    }
}

// ---------------------------------------------------------------------------
// Kernel 2: h = silu(xnh @ wh)  -- pure fp16, cp.async double-buffered
// ---------------------------------------------------------------------------
__global__ void gemm_uvqk_h() {
    __shared__ __align__(16) __half Ah[2][128 * 40];
    __shared__ __align__(16) __half Bh[2][32 * 72];
    int tid = threadIdx.x, lane = tid & 31, warp = tid >> 5;
    int wm = warp >> 1, wn = warp & 1;
    int m0 = blockIdx.y * 128, n0 = blockIdx.x * 64;

    float acc[2][4][4];
    #pragma unroll
    for (int a = 0; a < 2; a++)
        #pragma unroll
        for (int b = 0; b < 4; b++)
            #pragma unroll
            for (int c = 0; c < 4; c++) acc[a][b][c] = 0.f;

    unsigned abase0 = (unsigned)__cvta_generic_to_shared(Ah[0]);
    unsigned bbase0 = (unsigned)__cvta_generic_to_shared(Bh[0]);
    int a_row = lane & 15, a_col = (lane >> 4) * 8;
    int v_row = (lane & 7) + ((lane >> 3) & 1) * 8;
    int v_col = (lane >> 4) * 8;

    int ar[2], ac[2];
    #pragma unroll
    for (int it = 0; it < 2; it++) {
        int i = tid + it * 256;
        ar[it] = i >> 2; ac[it] = (i & 3) << 3;
    }
    int br = tid >> 3, bc = (tid & 7) << 3;

    #pragma unroll
    for (int it = 0; it < 2; it++)
        cpa16(abase0 + (ar[it] * 40 + ac[it]) * 2,
              g_xnh + (size_t)(m0 + ar[it]) * D_DIM + ac[it]);
    cpa16(bbase0 + (br * 72 + bc) * 2, g_wh + (size_t)br * HID + n0 + bc);
    asm volatile("cp.async.commit_group;");

    for (int ki = 0; ki < 16; ++ki) {
        int buf = ki & 1;
        asm volatile("cp.async.wait_group 0;");
        __syncthreads();
        if (ki < 15) {
            int k1 = (ki + 1) * 32;
            unsigned ab = abase0 + (buf ^ 1) * 128 * 40 * 2;
            unsigned bb = bbase0 + (buf ^ 1) * 32 * 72 * 2;
            #pragma unroll
            for (int it = 0; it < 2; it++)
                cpa16(ab + (ar[it] * 40 + ac[it]) * 2,
                      g_xnh + (size_t)(m0 + ar[it]) * D_DIM + k1 + ac[it]);
            cpa16(bb + (br * 72 + bc) * 2,
                  g_wh + (size_t)(k1 + br) * HID + n0 + bc);
            asm volatile("cp.async.commit_group;");
        }
        unsigned abase = abase0 + buf * 128 * 40 * 2;
        unsigned bbase = bbase0 + buf * 32 * 72 * 2;
        #pragma unroll
        for (int kc = 0; kc < 32; kc += 16) {
            unsigned af[2][4];
            ldsm4(af[0], abase + ((wm * 32 + a_row) * 40 + kc + a_col) * 2);
            ldsm4(af[1], abase + ((wm * 32 + 16 + a_row) * 40 + kc + a_col) * 2);
            #pragma unroll
            for (int n16 = 0; n16 < 2; n16++) {
                unsigned bf[4];
                ldsm4t(bf, bbase + ((kc + v_row) * 72 + wn * 32 + n16 * 16 + v_col) * 2);
                mma16(acc[0][n16 * 2],     af[0], bf[0], bf[1]);
                mma16(acc[0][n16 * 2 + 1], af[0], bf[2], bf[3]);
                mma16(acc[1][n16 * 2],     af[1], bf[0], bf[1]);
                mma16(acc[1][n16 * 2 + 1], af[1], bf[2], bf[3]);
            }
        }
    }
    int gid = lane >> 2, tig = lane & 3;
    int seg = n0 >> 8;
    __half* segp = (seg == 1) ? g_vh : (seg == 2) ? g_qh : g_kh;
    #pragma unroll
    for (int mm = 0; mm < 2; mm++) {
        #pragma unroll
        for (int nm = 0; nm < 4; nm++) {
            int r = m0 + wm * 32 + mm * 16 + gid;
            int c = (n0 & 255) + wn * 32 + nm * 8 + 2 * tig;
            float s0 = silu_f(acc[mm][nm][0]), s1 = silu_f(acc[mm][nm][1]);
            float s2 = silu_f(acc[mm][nm][2]), s3 = silu_f(acc[mm][nm][3]);
            if (seg == 0) {
                *(float2*)&g_u[(size_t)r * 256 + c] = make_float2(s0, s1);
                *(float2*)&g_u[(size_t)(r + 8) * 256 + c] = make_float2(s2, s3);
            } else {
                *(unsigned*)&segp[(size_t)r * 256 + c] = packh2(s0, s1);
                *(unsigned*)&segp[(size_t)(r + 8) * 256 + c] = packh2(s2, s3);
            }
        }
    }
}

// ---------------------------------------------------------------------------
// Kernel 3: jagged causal attention
// epilogue: octave-table bucket (exact, int thresholds) + f16x2 tanh silu
// ---------------------------------------------------------------------------
#define HS 72
#define KV_B 9216
#define SM_Q  0
#define SM_K0 9216
#define SM_V0 27648
#define SM_TW 46080
#define SM_TH 46608
#define SM_TQ 46672
#define SM_TK 46928
#define SM_OCT 47440              // 21 x int2
#define SM_TOT 47616

__global__ void __launch_bounds__(256, 2)
attn_mma(const int* __restrict__ ts, const float* __restrict__ tsw) {
    __shared__ __align__(16) unsigned char smb[SM_TOT];
    __half* Qh = (__half*)(smb + SM_Q);
    float*  red = (float*)smb;
    float*  tw  = (float*)(smb + SM_TW);
    float*  thf = (float*)(smb + SM_TH);
    int*    tqs = (int*)(smb + SM_TQ);
    int*    tkb = (int*)(smb + SM_TK);
    int2*   oct = (int2*)(smb + SM_OCT);

    int b  = c_ord[blockIdx.x][0];
    int qt = c_ord[blockIdx.x][1];
    int head = blockIdx.y;
    int tok0 = c_off[b] + qt * 64;

    int tid = threadIdx.x, lane = tid & 31, warp = tid >> 5;
    int wm = warp >> 1, wn = warp & 1;
    int i0 = wm * 16;
    int gid = lane >> 2, tig = lane & 3;

    unsigned qbase  = (unsigned)__cvta_generic_to_shared(smb + SM_Q);
    unsigned kbase0 = (unsigned)__cvta_generic_to_shared(smb + SM_K0);
    unsigned vbase0 = (unsigned)__cvta_generic_to_shared(smb + SM_V0);

    const __half* qb = g_qh + head * 64;
    const __half* kb = g_kh + head * 64;
    const __half* vb = g_vh + head * 64;

    #pragma unroll
    for (int it = 0; it < 2; it++) {
        int i = tid + it * 256;
        int r = i >> 3, c = (i & 7) << 3;
        *(uint4*)(Qh + r * HS + c) =
            *(const uint4*)(qb + (size_t)(tok0 + r) * 256 + c);
    }
    for (int i = tid; i < 129; i += 256) tw[i] = tsw[i];
    if (tid < 64) tqs[tid] = ts[b * N_SEQ + qt * 64 + tid];
    if (tid < 15) {
        if (tid == 0) thf[0] = 0.f;
        else {
            int k = tid;
            int t = (int)(expf((float)k)) - 9;
            if (t < 1) t = 1;
            while (t > 1 && log1pf((float)(t - 1)) >= (float)k) --t;
            while (log1pf((float)t) < (float)k) ++t;
            thf[k] = (float)t;
        }
    }

    {
        int ktok = c_off[b];
        #pragma unroll
        for (int it = 0; it < 2; it++) {
            int i = tid + it * 256;
            int r = i >> 3, c = (i & 7) << 3;
            unsigned soff = (unsigned)((r * HS + c) * 2);
            cpa16(kbase0 + soff, kb + (size_t)(ktok + r) * 256 + c);
            cpa16(vbase0 + soff, vb + (size_t)(ktok + r) * 256 + c);
        }
        asm volatile("cp.async.commit_group;");
        if (tid < 64) tkb[tid] = ts[b * N_SEQ + tid];
    }
    __syncthreads();

    // Octave table: for x=d+1 with exponent e, bucket(d) = base[e] + (d >= thr[e]).
    // Thresholds are exact integers -> int compares, no I2F in the hot loop.
    if (tid < 21) {
        int e = tid;
        float dlo = (float)((1u << e) - 1u);
        int base = 0;
        #pragma unroll
        for (int k = 1; k <= 14; k++) base += (dlo >= thf[k]) ? 1 : 0;
        int thr = (base < 14) ? (int)thf[base + 1] : 0x7fffffff;
        oct[e] = make_int2(base, thr);
    }
    __syncthreads();

    int tq0 = tqs[i0 + gid];
    int tq8 = tqs[i0 + gid + 8];

    float accO[8][4];
    #pragma unroll
    for (int t = 0; t < 8; t++)
        #pragma unroll
        for (int c = 0; c < 4; c++) accO[t][c] = 0.f;

    int a_row = lane & 15, a_col = (lane >> 4) * 8;
    int b_row = ((lane >> 4) * 8) + (lane & 7);
    int b_col = ((lane >> 3) & 1) * 8;
    int v_row = (lane & 7) + ((lane >> 3) & 1) * 8;
    int v_col = (lane >> 4) * 8;

    for (int jt = 0; jt <= qt; ++jt) {
        int bbuf = jt & 1;
        asm volatile("cp.async.wait_group 0;");
        __syncthreads();

        if (jt < qt) {
            int ktok = c_off[b] + (jt + 1) * 64;
            unsigned kb1 = kbase0 + (bbuf ^ 1) * KV_B;
            unsigned vb1 = vbase0 + (bbuf ^ 1) * KV_B;
            #pragma unroll
            for (int it = 0; it < 2; it++) {
                int i = tid + it * 256;
                int r = i >> 3, c = (i & 7) << 3;
                unsigned soff = (unsigned)((r * HS + c) * 2);
                cpa16(kb1 + soff, kb + (size_t)(ktok + r) * 256 + c);
                cpa16(vb1 + soff, vb + (size_t)(ktok + r) * 256 + c);
            }
            asm volatile("cp.async.commit_group;");
            if (tid < 64) tkb[(bbuf ^ 1) * 64 + tid] = ts[b * N_SEQ + (jt + 1) * 64 + tid];
        }

        unsigned kbase = kbase0 + bbuf * KV_B;
        unsigned vbase = vbase0 + bbuf * KV_B;
        const int* tks = tkb + bbuf * 64;

        float accS[4][4];
        #pragma unroll
        for (int a = 0; a < 4; a++)
            #pragma unroll
            for (int c = 0; c < 4; c++) accS[a][c] = 0.f;
        #pragma unroll
        for (int kc = 0; kc < 4; kc++) {
            int d0 = kc * 16;
            unsigned af[4];
            ldsm4(af, qbase + ((i0 + a_row) * HS + d0 + a_col) * 2);
            #pragma unroll
            for (int hh = 0; hh < 2; hh++) {
                int j0 = wn * 32 + hh * 16;
                unsigned bf[4];
                ldsm4(bf, kbase + ((j0 + b_row) * HS + d0 + b_col) * 2);
                mma16(accS[hh * 2],     af, bf[0], bf[1]);
                mma16(accS[hh * 2 + 1], af, bf[2], bf[3]);
            }
        }

        // ---- epilogue: bias + silu(f16x2) + causal -> pa fragments directly
        bool full = (jt < qt);
        unsigned pa[2][4];
        #pragma unroll
        for (int nm = 0; nm < 4; nm++) {
            int jb = wn * 32 + nm * 8 + tig * 2;
            int2 tk2 = *(const int2*)&tks[jb];
            int d0 = tq0 - tk2.x; d0 = (d0 < 0) ? -d0 : d0;
            int d1 = tq0 - tk2.y; d1 = (d1 < 0) ? -d1 : d1;
            int d2 = tq8 - tk2.x; d2 = (d2 < 0) ? -d2 : d2;
            int d3 = tq8 - tk2.y; d3 = (d3 < 0) ? -d3 : d3;
            int2 o0 = oct[31 - __clz(d0 + 1)];
            int2 o1 = oct[31 - __clz(d1 + 1)];
            int2 o2 = oct[31 - __clz(d2 + 1)];
            int2 o3 = oct[31 - __clz(d3 + 1)];
            float s0 = accS[nm][0] + tw[o0.x + ((d0 >= o0.y) ? 1 : 0)];
            float s1 = accS[nm][1] + tw[o1.x + ((d1 >= o1.y) ? 1 : 0)];
            float s2 = accS[nm][2] + tw[o2.x + ((d2 >= o2.y) ? 1 : 0)];
            float s3 = accS[nm][3] + tw[o3.x + ((d3 >= o3.y) ? 1 : 0)];
            if (!full) {           // warp-uniform: only the diagonal tile
                int ilo = i0 + gid, ihi = ilo + 8;
                if (jb     > ilo) s0 = 0.f;
                if (jb + 1 > ilo) s1 = 0.f;
                if (jb     > ihi) s2 = 0.f;
                if (jb + 1 > ihi) s3 = 0.f;
            }
            unsigned* pd = &pa[nm >> 1][(nm & 1) * 2];
            pd[0] = silu2(s0, s1);
            pd[1] = silu2(s2, s3);
        }

        #pragma unroll
        for (int kc = 0; kc < 2; kc++) {
            int jc = wn * 32 + kc * 16;
            #pragma unroll
            for (int lt = 0; lt < 4; lt++) {
                int l0 = lt * 16;
                unsigned bf[4];
                ldsm4t(bf, vbase + ((jc + v_row) * HS + l0 + v_col) * 2);
                mma16(accO[lt * 2],     pa[kc], bf[0], bf[1]);
                mma16(accO[lt * 2 + 1], pa[kc], bf[2], bf[3]);
            }
        }
    }

    __syncthreads();
    if (wn == 1) {
        #pragma unroll
        for (int t = 0; t < 8; t++)
            #pragma unroll
            for (int e = 0; e < 4; e++)
                red[((t * 4 + e) * 4 + wm) * 32 + lane] = accO[t][e];
    }
    __syncthreads();
    if (wn == 0) {
        #pragma unroll
        for (int t = 0; t < 8; t++)
            #pragma unroll
            for (int e = 0; e < 4; e++)
                accO[t][e] += red[((t * 4 + e) * 4 + wm) * 32 + lane];
        #pragma unroll
        for (int nt = 0; nt < 8; nt++) {
            int i = tok0 + i0 + gid;
            int l = head * 64 + nt * 8 + tig * 2;
            *(float2*)&g_attn[(size_t)i * 256 + l] =
                make_float2(accO[nt][0] * INV_N, accO[nt][1] * INV_N);
            *(float2*)&g_attn[(size_t)(i + 8) * 256 + l] =
                make_float2(accO[nt][2] * INV_N, accO[nt][3] * INV_N);
        }
    }
}

// ---------------------------------------------------------------------------
// Kernel 4: oin = u * LN(attn), warp-per-token, fp16 output
// ---------------------------------------------------------------------------
__global__ void oin_kernel() {
    int t = blockIdx.x * 8 + (threadIdx.x >> 5);
    int lane = threadIdx.x & 31;
    const float* row = g_attn + (size_t)t * 256 + lane * 4;
    float4 a0 = *(const float4*)(row);
    float4 a1 = *(const float4*)(row + 128);
    float s = a0.x + a0.y + a0.z + a0.w + a1.x + a1.y + a1.z + a1.w;
    float q = a0.x*a0.x + a0.y*a0.y + a0.z*a0.z + a0.w*a0.w
            + a1.x*a1.x + a1.y*a1.y + a1.z*a1.z + a1.w*a1.w;
    #pragma unroll
    for (int o = 16; o > 0; o >>= 1) {
        s += __shfl_xor_sync(0xffffffffu, s, o);
        q += __shfl_xor_sync(0xffffffffu, q, o);
    }
    float m = s * (1.0f / 256.0f);
    float r = rsqrtf(q * (1.0f / 256.0f) - m * m + EPS);
    const float* up = g_u + (size_t)t * 256 + lane * 4;
    float4 u0 = *(const float4*)(up);
    float4 u1 = *(const float4*)(up + 128);
    __half* dst = g_oinh + (size_t)t * 256 + lane * 4;
    *(uint2*)(dst) = make_uint2(
        packh2(u0.x * (a0.x - m) * r, u0.y * (a0.y - m) * r),
        packh2(u0.z * (a0.z - m) * r, u0.w * (a0.w - m) * r));
    *(uint2*)(dst + 128) = make_uint2(
        packh2(u1.x * (a1.x - m) * r, u1.y * (a1.y - m) * r),
        packh2(u1.z * (a1.z - m) * r, u1.w * (a1.w - m) * r));
}

// ---------------------------------------------------------------------------
// Kernel 5: out = oinh @ owh^T + o_b + x  -- pure fp16, cp.async pipelined
// ---------------------------------------------------------------------------
__global__ void gemm_out_h(const float* __restrict__ bias,
                           const float* __restrict__ x,
                           float* __restrict__ out) {
    __shared__ __align__(16) __half Ah[2][128 * 40];
    __shared__ __align__(16) __half Wh[2][64 * 40];
    int tid = threadIdx.x, lane = tid & 31, warp = tid >> 5;
    int wm = warp >> 1, wn = warp & 1;
    int m0 = blockIdx.y * 128, n0 = blockIdx.x * 64;

    float acc[2][4][4];
    #pragma unroll
    for (int a = 0; a < 2; a++)
        #pragma unroll
        for (int b = 0; b < 4; b++)
            #pragma unroll
            for (int c = 0; c < 4; c++) acc[a][b][c] = 0.f;

    unsigned abase0 = (unsigned)__cvta_generic_to_shared(Ah[0]);
    unsigned wbase0 = (unsigned)__cvta_generic_to_shared(Wh[0]);
    int a_row = lane & 15, a_col = (lane >> 4) * 8;
    int b_row = ((lane >> 4) * 8) + (lane & 7);
    int b_col = ((lane >> 3) & 1) * 8;

    int ar[2], ac[2];
    #pragma unroll
    for (int it = 0; it < 2; it++) {
        int i = tid + it * 256;
        ar[it] = i >> 2; ac[it] = (i & 3) << 3;
    }
    int wr = tid >> 2, wc = (tid & 3) << 3;

    #pragma unroll
    for (int it = 0; it < 2; it++)
        cpa16(abase0 + (ar[it] * 40 + ac[it]) * 2,
              g_oinh + (size_t)(m0 + ar[it]) * 256 + ac[it]);
    cpa16(wbase0 + (wr * 40 + wc) * 2, g_owh + (size_t)(n0 + wr) * 256 + wc);
    asm volatile("cp.async.commit_group;");

    for (int ki = 0; ki < 8; ++ki) {
        int buf = ki & 1;
        asm volatile("cp.async.wait_group 0;");
        __syncthreads();
        if (ki < 7) {
            int k1 = (ki + 1) * 32;
            unsigned ab = abase0 + (buf ^ 1) * 128 * 40 * 2;
            unsigned wb = wbase0 + (buf ^ 1) * 64 * 40 * 2;
            #pragma unroll
            for (int it = 0; it < 2; it++)
                cpa16(ab + (ar[it] * 40 + ac[it]) * 2,
                      g_oinh + (size_t)(m0 + ar[it]) * 256 + k1 + ac[it]);
            cpa16(wb + (wr * 40 + wc) * 2,
                  g_owh + (size_t)(n0 + wr) * 256 + k1 + wc);
            asm volatile("cp.async.commit_group;");
        }
        unsigned abase = abase0 + buf * 128 * 40 * 2;
        unsigned wbase = wbase0 + buf * 64 * 40 * 2;
        #pragma unroll
        for (int kc = 0; kc < 32; kc += 16) {
            unsigned af[2][4];
            ldsm4(af[0], abase + ((wm * 32 + a_row) * 40 + kc + a_col) * 2);
            ldsm4(af[1], abase + ((wm * 32 + 16 + a_row) * 40 + kc + a_col) * 2);
            #pragma unroll
            for (int n16 = 0; n16 < 2; n16++) {
                unsigned bf[4];
                ldsm4(bf, wbase + ((wn * 32 + n16 * 16 + b_row) * 40 + kc + b_col) * 2);
                mma16(acc[0][n16 * 2],     af[0], bf[0], bf[1]);
                mma16(acc[0][n16 * 2 + 1], af[0], bf[2], bf[3]);
                mma16(acc[1][n16 * 2],     af[1], bf[0], bf[1]);
                mma16(acc[1][n16 * 2 + 1], af[1], bf[2], bf[3]);
            }
        }
    }
    int gid = lane >> 2, tig = lane & 3;
    #pragma unroll
    for (int mm = 0; mm < 2; mm++) {
        #pragma unroll
        for (int nm = 0; nm < 4; nm++) {
            int r = m0 + wm * 32 + mm * 16 + gid;
            int c = n0 + wn * 32 + nm * 8 + 2 * tig;
            float2 xr0 = *(const float2*)&x[(size_t)r * D_DIM + c];
            float2 xr1 = *(const float2*)&x[(size_t)(r + 8) * D_DIM + c];
            float b0 = bias[c], b1 = bias[c + 1];
            *(float2*)&out[(size_t)r * D_DIM + c] =
                make_float2(acc[mm][nm][0] + b0 + xr0.x, acc[mm][nm][1] + b1 + xr0.y);
            *(float2*)&out[(size_t)(r + 8) * D_DIM + c] =
                make_float2(acc[mm][nm][2] + b0 + xr1.x, acc[mm][nm][3] + b1 + xr1.y);
        }
    }
}

// ---------------------------------------------------------------------------
// Launcher
// ---------------------------------------------------------------------------
extern "C" void kernel_launch(void* const* d_in, const int* in_sizes, int n_in,
                              void* d_out, int out_size) {
    const float* x    = (const float*)d_in[0];
    const float* uvqk = (const float*)d_in[1];
    const float* o_w  = (const float*)d_in[2];
    const float* o_b  = (const float*)d_in[3];
    const float* ts_w = (const float*)d_in[4];
    const int*   ts   = (const int*)d_in[5];
    float* out = (float*)d_out;

    convert_w_kernel<<<640, 256>>>(uvqk, o_w);
    ln_x_kernel<<<T_TOK / 8, 256>>>(x);
    gemm_uvqk_h<<<dim3(HID / 64, T_TOK / 128), 256>>>();
    attn_mma<<<dim3(100, 4), 256>>>(ts, ts_w);
    oin_kernel<<<T_TOK / 8, 256>>>();
    gemm_out_h<<<dim3(D_DIM / 64, T_TOK / 128), 256>>>(o_b, x, out);
}

// round 14
// speedup vs baseline: 1.5241x; 1.5241x over previous
#include <cuda_runtime.h>
#include <cuda_bf16.h>
#include <cuda_fp16.h>
#include <math.h>

// ---------------------------------------------------------------------------
// Problem constants
// ---------------------------------------------------------------------------
#define T_TOK   6400
#define D_DIM   512
#define HID     1024
#define N_SEQ   2048
#define EPS     1e-6f
#define INV_N   (1.0f/2048.0f)

__device__ __constant__ int c_off[5] = {0, 2048, 3584, 4608, 6400};
__device__ __constant__ unsigned char c_ord[100][2] = {
 {0,31},{0,30},{0,29},{0,28},
 {0,27},{3,27},{0,26},{3,26},{0,25},{3,25},{0,24},{3,24},
 {0,23},{1,23},{3,23},{0,22},{1,22},{3,22},{0,21},{1,21},{3,21},
 {0,20},{1,20},{3,20},{0,19},{1,19},{3,19},{0,18},{1,18},{3,18},
 {0,17},{1,17},{3,17},{0,16},{1,16},{3,16},
 {0,15},{1,15},{2,15},{3,15},{0,14},{1,14},{2,14},{3,14},
 {0,13},{1,13},{2,13},{3,13},{0,12},{1,12},{2,12},{3,12},
 {0,11},{1,11},{2,11},{3,11},{0,10},{1,10},{2,10},{3,10},
 {0,9},{1,9},{2,9},{3,9},{0,8},{1,8},{2,8},{3,8},
 {0,7},{1,7},{2,7},{3,7},{0,6},{1,6},{2,6},{3,6},
 {0,5},{1,5},{2,5},{3,5},{0,4},{1,4},{2,4},{3,4},
 {0,3},{1,3},{2,3},{3,3},{0,2},{1,2},{2,2},{3,2},
 {0,1},{1,1},{2,1},{3,1},{0,0},{1,0},{2,0},{3,0}};

// ---------------------------------------------------------------------------
// Scratch
// ---------------------------------------------------------------------------
__device__ __half g_xnh [T_TOK * D_DIM];
__device__ __half g_wh  [D_DIM * HID];
__device__ __half g_owh [D_DIM * 256];
__device__ float  g_u   [T_TOK * 256];
__device__ __half g_qh  [T_TOK * 256];
__device__ __half g_kh  [T_TOK * 256];
__device__ __half g_vh  [T_TOK * 256];
__device__ float  g_attn[T_TOK * 256];
__device__ __half g_oinh[T_TOK * 256];

// ---------------------------------------------------------------------------
// helpers
// ---------------------------------------------------------------------------
__device__ __forceinline__ void mma16(float* c, const unsigned* a, unsigned b0, unsigned b1) {
    asm volatile(
      "mma.sync.aligned.m16n8k16.row.col.f32.f16.f16.f32 "
      "{%0,%1,%2,%3}, {%4,%5,%6,%7}, {%8,%9}, {%0,%1,%2,%3};"
      : "+f"(c[0]), "+f"(c[1]), "+f"(c[2]), "+f"(c[3])
      : "r"(a[0]), "r"(a[1]), "r"(a[2]), "r"(a[3]), "r"(b0), "r"(b1));
}
__device__ __forceinline__ void ldsm4(unsigned* r, unsigned addr) {
    asm volatile("ldmatrix.sync.aligned.m8n8.x4.shared.b16 {%0,%1,%2,%3}, [%4];"
        : "=r"(r[0]), "=r"(r[1]), "=r"(r[2]), "=r"(r[3]) : "r"(addr));
}
__device__ __forceinline__ void ldsm4t(unsigned* r, unsigned addr) {
    asm volatile("ldmatrix.sync.aligned.m8n8.x4.trans.shared.b16 {%0,%1,%2,%3}, [%4];"
        : "=r"(r[0]), "=r"(r[1]), "=r"(r[2]), "=r"(r[3]) : "r"(addr));
}
__device__ __forceinline__ void cpa16(unsigned saddr, const void* g) {
    asm volatile("cp.async.ca.shared.global [%0], [%1], 16;" :: "r"(saddr), "l"(g));
}
__device__ __forceinline__ unsigned packh2(float x, float y) {
    __half2 h = __floats2half2_rn(x, y);
    return *(unsigned*)&h;
}
__device__ __forceinline__ float silu_f(float s) {
    return s * __fdividef(1.0f, 1.0f + __expf(-s));
}
// silu on a float pair, computed in half2 (1 MUFU), returns packed half2 == pa frag
__device__ __forceinline__ unsigned silu2(float a, float b) {
    __half2 h05 = __floats2half2_rn(0.5f, 0.5f);
    __half2 s = __floats2half2_rn(a, b);
    __half2 arg = __hmul2(s, h05);
    unsigned t;
    asm("tanh.approx.f16x2 %0, %1;" : "=r"(t) : "r"(*(unsigned*)&arg));
    __half2 sig = __hfma2(*(__half2*)&t, h05, h05);
    __half2 p = __hmul2(s, sig);
    return *(unsigned*)&p;
}

// ---------------------------------------------------------------------------
// Kernel 1: fused LN(x)->fp16  +  weight fp16 conversion
// blocks [0,800): layernorm; blocks [800,1440): convert uvqk/o_w
// ---------------------------------------------------------------------------
__global__ void ln_conv_kernel(const float* __restrict__ x,
                               const float* __restrict__ uvqk,
                               const float* __restrict__ ow) {
    if (blockIdx.x >= 800) {
        int cb = blockIdx.x - 800;
        int i = cb * 1024 + threadIdx.x * 4;
        if (cb < 512) {
            float4 v = *(const float4*)(uvqk + i);
            *(uint2*)&g_wh[i] = make_uint2(packh2(v.x, v.y), packh2(v.z, v.w));
        } else {
            int j = i - 512 * 1024;
            float4 v = *(const float4*)(ow + j);
            *(uint2*)&g_owh[j] = make_uint2(packh2(v.x, v.y), packh2(v.z, v.w));
        }
        return;
    }
    int t = blockIdx.x * 8 + (threadIdx.x >> 5);
    int lane = threadIdx.x & 31;
    const float* row = x + (size_t)t * D_DIM + lane * 4;
    float4 v[4];
    #pragma unroll
    for (int w = 0; w < 4; w++) v[w] = *(const float4*)(row + w * 128);
    float s = 0.f, q = 0.f;
    #pragma unroll
    for (int w = 0; w < 4; w++) {
        s += v[w].x + v[w].y + v[w].z + v[w].w;
        q += v[w].x*v[w].x + v[w].y*v[w].y + v[w].z*v[w].z + v[w].w*v[w].w;
    }
    #pragma unroll
    for (int o = 16; o > 0; o >>= 1) {
        s += __shfl_xor_sync(0xffffffffu, s, o);
        q += __shfl_xor_sync(0xffffffffu, q, o);
    }
    float m = s * (1.0f / D_DIM);
    float r = rsqrtf(q * (1.0f / D_DIM) - m * m + EPS);
    __half* dst = g_xnh + (size_t)t * D_DIM + lane * 4;
    #pragma unroll
    for (int w = 0; w < 4; w++) {
        *(uint2*)(dst + w * 128) = make_uint2(
            packh2((v[w].x - m) * r, (v[w].y - m) * r),
            packh2((v[w].z - m) * r, (v[w].w - m) * r));
    }
}

// ---------------------------------------------------------------------------
// Kernel 2: h = silu(xnh @ wh)  -- pure fp16, cp.async double-buffered
// ---------------------------------------------------------------------------
__global__ void gemm_uvqk_h() {
    __shared__ __align__(16) __half Ah[2][128 * 40];
    __shared__ __align__(16) __half Bh[2][32 * 72];
    int tid = threadIdx.x, lane = tid & 31, warp = tid >> 5;
    int wm = warp >> 1, wn = warp & 1;
    int m0 = blockIdx.y * 128, n0 = blockIdx.x * 64;

    float acc[2][4][4];
    #pragma unroll
    for (int a = 0; a < 2; a++)
        #pragma unroll
        for (int b = 0; b < 4; b++)
            #pragma unroll
            for (int c = 0; c < 4; c++) acc[a][b][c] = 0.f;

    unsigned abase0 = (unsigned)__cvta_generic_to_shared(Ah[0]);
    unsigned bbase0 = (unsigned)__cvta_generic_to_shared(Bh[0]);
    int a_row = lane & 15, a_col = (lane >> 4) * 8;
    int v_row = (lane & 7) + ((lane >> 3) & 1) * 8;
    int v_col = (lane >> 4) * 8;

    int ar[2], ac[2];
    #pragma unroll
    for (int it = 0; it < 2; it++) {
        int i = tid + it * 256;
        ar[it] = i >> 2; ac[it] = (i & 3) << 3;
    }
    int br = tid >> 3, bc = (tid & 7) << 3;

    #pragma unroll
    for (int it = 0; it < 2; it++)
        cpa16(abase0 + (ar[it] * 40 + ac[it]) * 2,
              g_xnh + (size_t)(m0 + ar[it]) * D_DIM + ac[it]);
    cpa16(bbase0 + (br * 72 + bc) * 2, g_wh + (size_t)br * HID + n0 + bc);
    asm volatile("cp.async.commit_group;");

    for (int ki = 0; ki < 16; ++ki) {
        int buf = ki & 1;
        asm volatile("cp.async.wait_group 0;");
        __syncthreads();
        if (ki < 15) {
            int k1 = (ki + 1) * 32;
            unsigned ab = abase0 + (buf ^ 1) * 128 * 40 * 2;
            unsigned bb = bbase0 + (buf ^ 1) * 32 * 72 * 2;
            #pragma unroll
            for (int it = 0; it < 2; it++)
                cpa16(ab + (ar[it] * 40 + ac[it]) * 2,
                      g_xnh + (size_t)(m0 + ar[it]) * D_DIM + k1 + ac[it]);
            cpa16(bb + (br * 72 + bc) * 2,
                  g_wh + (size_t)(k1 + br) * HID + n0 + bc);
            asm volatile("cp.async.commit_group;");
        }
        unsigned abase = abase0 + buf * 128 * 40 * 2;
        unsigned bbase = bbase0 + buf * 32 * 72 * 2;
        #pragma unroll
        for (int kc = 0; kc < 32; kc += 16) {
            unsigned af[2][4];
            ldsm4(af[0], abase + ((wm * 32 + a_row) * 40 + kc + a_col) * 2);
            ldsm4(af[1], abase + ((wm * 32 + 16 + a_row) * 40 + kc + a_col) * 2);
            #pragma unroll
            for (int n16 = 0; n16 < 2; n16++) {
                unsigned bf[4];
                ldsm4t(bf, bbase + ((kc + v_row) * 72 + wn * 32 + n16 * 16 + v_col) * 2);
                mma16(acc[0][n16 * 2],     af[0], bf[0], bf[1]);
                mma16(acc[0][n16 * 2 + 1], af[0], bf[2], bf[3]);
                mma16(acc[1][n16 * 2],     af[1], bf[0], bf[1]);
                mma16(acc[1][n16 * 2 + 1], af[1], bf[2], bf[3]);
            }
        }
    }
    int gid = lane >> 2, tig = lane & 3;
    int seg = n0 >> 8;
    __half* segp = (seg == 1) ? g_vh : (seg == 2) ? g_qh : g_kh;
    #pragma unroll
    for (int mm = 0; mm < 2; mm++) {
        #pragma unroll
        for (int nm = 0; nm < 4; nm++) {
            int r = m0 + wm * 32 + mm * 16 + gid;
            int c = (n0 & 255) + wn * 32 + nm * 8 + 2 * tig;
            float s0 = silu_f(acc[mm][nm][0]), s1 = silu_f(acc[mm][nm][1]);
            float s2 = silu_f(acc[mm][nm][2]), s3 = silu_f(acc[mm][nm][3]);
            if (seg == 0) {
                *(float2*)&g_u[(size_t)r * 256 + c] = make_float2(s0, s1);
                *(float2*)&g_u[(size_t)(r + 8) * 256 + c] = make_float2(s2, s3);
            } else {
                *(unsigned*)&segp[(size_t)r * 256 + c] = packh2(s0, s1);
                *(unsigned*)&segp[(size_t)(r + 8) * 256 + c] = packh2(s2, s3);
            }
        }
    }
}

// ---------------------------------------------------------------------------
// Kernel 3: jagged causal attention (R13 epilogue; hoisted cp.async offsets)
// ---------------------------------------------------------------------------
#define HS 72
#define KV_B 9216
#define SM_Q  0
#define SM_K0 9216
#define SM_V0 27648
#define SM_TW 46080
#define SM_TH 46608
#define SM_TQ 46672
#define SM_TK 46928
#define SM_OCT 47440
#define SM_TOT 47616

__global__ void __launch_bounds__(256, 2)
attn_mma(const int* __restrict__ ts, const float* __restrict__ tsw) {
    __shared__ __align__(16) unsigned char smb[SM_TOT];
    __half* Qh = (__half*)(smb + SM_Q);
    float*  red = (float*)smb;
    float*  tw  = (float*)(smb + SM_TW);
    float*  thf = (float*)(smb + SM_TH);
    int*    tqs = (int*)(smb + SM_TQ);
    int*    tkb = (int*)(smb + SM_TK);
    int2*   oct = (int2*)(smb + SM_OCT);

    int b  = c_ord[blockIdx.x][0];
    int qt = c_ord[blockIdx.x][1];
    int head = blockIdx.y;
    int tok0 = c_off[b] + qt * 64;

    int tid = threadIdx.x, lane = tid & 31, warp = tid >> 5;
    int wm = warp >> 1, wn = warp & 1;
    int i0 = wm * 16;
    int gid = lane >> 2, tig = lane & 3;

    unsigned qbase  = (unsigned)__cvta_generic_to_shared(smb + SM_Q);
    unsigned kbase0 = (unsigned)__cvta_generic_to_shared(smb + SM_K0);
    unsigned vbase0 = (unsigned)__cvta_generic_to_shared(smb + SM_V0);

    // hoisted per-thread copy geometry (loop-invariant)
    int cr0 = tid >> 3, cc0 = (tid & 7) << 3;              // it=0
    int cr1 = (tid + 256) >> 3, cc1 = ((tid + 256) & 7) << 3;
    unsigned soff0 = (unsigned)((cr0 * HS + cc0) * 2);
    unsigned soff1 = (unsigned)((cr1 * HS + cc1) * 2);
    size_t goff0 = (size_t)cr0 * 256 + cc0;
    size_t goff1 = (size_t)cr1 * 256 + cc1;

    const __half* qb = g_qh + head * 64;
    const __half* kp = g_kh + head * 64 + (size_t)c_off[b] * 256;  // running base
    const __half* vp = g_vh + head * 64 + (size_t)c_off[b] * 256;

    *(uint4*)(Qh + (soff0 >> 1)) = *(const uint4*)(qb + (size_t)(tok0) * 256 + goff0);
    *(uint4*)(Qh + (soff1 >> 1)) = *(const uint4*)(qb + (size_t)(tok0) * 256 + goff1);
    for (int i = tid; i < 129; i += 256) tw[i] = tsw[i];
    if (tid < 64) tqs[tid] = ts[b * N_SEQ + qt * 64 + tid];
    if (tid < 15) {
        if (tid == 0) thf[0] = 0.f;
        else {
            int k = tid;
            int t = (int)(expf((float)k)) - 9;
            if (t < 1) t = 1;
            while (t > 1 && log1pf((float)(t - 1)) >= (float)k) --t;
            while (log1pf((float)t) < (float)k) ++t;
            thf[k] = (float)t;
        }
    }

    // prologue: jt = 0 into buffer 0
    cpa16(kbase0 + soff0, kp + goff0);
    cpa16(kbase0 + soff1, kp + goff1);
    cpa16(vbase0 + soff0, vp + goff0);
    cpa16(vbase0 + soff1, vp + goff1);
    asm volatile("cp.async.commit_group;");
    if (tid < 64) tkb[tid] = ts[b * N_SEQ + tid];
    __syncthreads();

    if (tid < 21) {
        int e = tid;
        float dlo = (float)((1u << e) - 1u);
        int base = 0;
        #pragma unroll
        for (int k = 1; k <= 14; k++) base += (dlo >= thf[k]) ? 1 : 0;
        int thr = (base < 14) ? (int)thf[base + 1] : 0x7fffffff;
        oct[e] = make_int2(base, thr);
    }
    __syncthreads();

    int tq0 = tqs[i0 + gid];
    int tq8 = tqs[i0 + gid + 8];

    float accO[8][4];
    #pragma unroll
    for (int t = 0; t < 8; t++)
        #pragma unroll
        for (int c = 0; c < 4; c++) accO[t][c] = 0.f;

    int a_row = lane & 15, a_col = (lane >> 4) * 8;
    int b_row = ((lane >> 4) * 8) + (lane & 7);
    int b_col = ((lane >> 3) & 1) * 8;
    int v_row = (lane & 7) + ((lane >> 3) & 1) * 8;
    int v_col = (lane >> 4) * 8;

    for (int jt = 0; jt <= qt; ++jt) {
        int bbuf = jt & 1;
        asm volatile("cp.async.wait_group 0;");
        __syncthreads();

        if (jt < qt) {
            size_t nk = (size_t)(jt + 1) * 64 * 256;
            unsigned kb1 = kbase0 + (bbuf ^ 1) * KV_B;
            unsigned vb1 = vbase0 + (bbuf ^ 1) * KV_B;
            cpa16(kb1 + soff0, kp + nk + goff0);
            cpa16(kb1 + soff1, kp + nk + goff1);
            cpa16(vb1 + soff0, vp + nk + goff0);
            cpa16(vb1 + soff1, vp + nk + goff1);
            asm volatile("cp.async.commit_group;");
            if (tid < 64) tkb[(bbuf ^ 1) * 64 + tid] = ts[b * N_SEQ + (jt + 1) * 64 + tid];
        }

        unsigned kbase = kbase0 + bbuf * KV_B;
        unsigned vbase = vbase0 + bbuf * KV_B;
        const int* tks = tkb + bbuf * 64;

        float accS[4][4];
        #pragma unroll
        for (int a = 0; a < 4; a++)
            #pragma unroll
            for (int c = 0; c < 4; c++) accS[a][c] = 0.f;
        #pragma unroll
        for (int kc = 0; kc < 4; kc++) {
            int d0 = kc * 16;
            unsigned af[4];
            ldsm4(af, qbase + ((i0 + a_row) * HS + d0 + a_col) * 2);
            #pragma unroll
            for (int hh = 0; hh < 2; hh++) {
                int j0 = wn * 32 + hh * 16;
                unsigned bf[4];
                ldsm4(bf, kbase + ((j0 + b_row) * HS + d0 + b_col) * 2);
                mma16(accS[hh * 2],     af, bf[0], bf[1]);
                mma16(accS[hh * 2 + 1], af, bf[2], bf[3]);
            }
        }

        bool full = (jt < qt);
        unsigned pa[2][4];
        #pragma unroll
        for (int nm = 0; nm < 4; nm++) {
            int jb = wn * 32 + nm * 8 + tig * 2;
            int2 tk2 = *(const int2*)&tks[jb];
            int d0 = tq0 - tk2.x; d0 = (d0 < 0) ? -d0 : d0;
            int d1 = tq0 - tk2.y; d1 = (d1 < 0) ? -d1 : d1;
            int d2 = tq8 - tk2.x; d2 = (d2 < 0) ? -d2 : d2;
            int d3 = tq8 - tk2.y; d3 = (d3 < 0) ? -d3 : d3;
            int2 o0 = oct[31 - __clz(d0 + 1)];
            int2 o1 = oct[31 - __clz(d1 + 1)];
            int2 o2 = oct[31 - __clz(d2 + 1)];
            int2 o3 = oct[31 - __clz(d3 + 1)];
            float s0 = accS[nm][0] + tw[o0.x + ((d0 >= o0.y) ? 1 : 0)];
            float s1 = accS[nm][1] + tw[o1.x + ((d1 >= o1.y) ? 1 : 0)];
            float s2 = accS[nm][2] + tw[o2.x + ((d2 >= o2.y) ? 1 : 0)];
            float s3 = accS[nm][3] + tw[o3.x + ((d3 >= o3.y) ? 1 : 0)];
            if (!full) {
                int ilo = i0 + gid, ihi = ilo + 8;
                if (jb     > ilo) s0 = 0.f;
                if (jb + 1 > ilo) s1 = 0.f;
                if (jb     > ihi) s2 = 0.f;
                if (jb + 1 > ihi) s3 = 0.f;
            }
            unsigned* pd = &pa[nm >> 1][(nm & 1) * 2];
            pd[0] = silu2(s0, s1);
            pd[1] = silu2(s2, s3);
        }

        #pragma unroll
        for (int kc = 0; kc < 2; kc++) {
            int jc = wn * 32 + kc * 16;
            #pragma unroll
            for (int lt = 0; lt < 4; lt++) {
                int l0 = lt * 16;
                unsigned bf[4];
                ldsm4t(bf, vbase + ((jc + v_row) * HS + l0 + v_col) * 2);
                mma16(accO[lt * 2],     pa[kc], bf[0], bf[1]);
                mma16(accO[lt * 2 + 1], pa[kc], bf[2], bf[3]);
            }
        }
    }

    __syncthreads();
    if (wn == 1) {
        #pragma unroll
        for (int t = 0; t < 8; t++)
            #pragma unroll
            for (int e = 0; e < 4; e++)
                red[((t * 4 + e) * 4 + wm) * 32 + lane] = accO[t][e];
    }
    __syncthreads();
    if (wn == 0) {
        #pragma unroll
        for (int t = 0; t < 8; t++)
            #pragma unroll
            for (int e = 0; e < 4; e++)
                accO[t][e] += red[((t * 4 + e) * 4 + wm) * 32 + lane];
        #pragma unroll
        for (int nt = 0; nt < 8; nt++) {
            int i = tok0 + i0 + gid;
            int l = head * 64 + nt * 8 + tig * 2;
            *(float2*)&g_attn[(size_t)i * 256 + l] =
                make_float2(accO[nt][0] * INV_N, accO[nt][1] * INV_N);
            *(float2*)&g_attn[(size_t)(i + 8) * 256 + l] =
                make_float2(accO[nt][2] * INV_N, accO[nt][3] * INV_N);
        }
    }
}

// ---------------------------------------------------------------------------
// Kernel 4: oin = u * LN(attn), warp-per-token, fp16 output
// ---------------------------------------------------------------------------
__global__ void oin_kernel() {
    int t = blockIdx.x * 8 + (threadIdx.x >> 5);
    int lane = threadIdx.x & 31;
    const float* row = g_attn + (size_t)t * 256 + lane * 4;
    float4 a0 = *(const float4*)(row);
    float4 a1 = *(const float4*)(row + 128);
    float s = a0.x + a0.y + a0.z + a0.w + a1.x + a1.y + a1.z + a1.w;
    float q = a0.x*a0.x + a0.y*a0.y + a0.z*a0.z + a0.w*a0.w
            + a1.x*a1.x + a1.y*a1.y + a1.z*a1.z + a1.w*a1.w;
    #pragma unroll
    for (int o = 16; o > 0; o >>= 1) {
        s += __shfl_xor_sync(0xffffffffu, s, o);
        q += __shfl_xor_sync(0xffffffffu, q, o);
    }
    float m = s * (1.0f / 256.0f);
    float r = rsqrtf(q * (1.0f / 256.0f) - m * m + EPS);
    const float* up = g_u + (size_t)t * 256 + lane * 4;
    float4 u0 = *(const float4*)(up);
    float4 u1 = *(const float4*)(up + 128);
    __half* dst = g_oinh + (size_t)t * 256 + lane * 4;
    *(uint2*)(dst) = make_uint2(
        packh2(u0.x * (a0.x - m) * r, u0.y * (a0.y - m) * r),
        packh2(u0.z * (a0.z - m) * r, u0.w * (a0.w - m) * r));
    *(uint2*)(dst + 128) = make_uint2(
        packh2(u1.x * (a1.x - m) * r, u1.y * (a1.y - m) * r),
        packh2(u1.z * (a1.z - m) * r, u1.w * (a1.w - m) * r));
}

// ---------------------------------------------------------------------------
// Kernel 5: out = oinh @ owh^T + o_b + x  -- pure fp16, cp.async pipelined
// ---------------------------------------------------------------------------
__global__ void gemm_out_h(const float* __restrict__ bias,
                           const float* __restrict__ x,
                           float* __restrict__ out) {
    __shared__ __align__(16) __half Ah[2][128 * 40];
    __shared__ __align__(16) __half Wh[2][64 * 40];
    int tid = threadIdx.x, lane = tid & 31, warp = tid >> 5;
    int wm = warp >> 1, wn = warp & 1;
    int m0 = blockIdx.y * 128, n0 = blockIdx.x * 64;

    float acc[2][4][4];
    #pragma unroll
    for (int a = 0; a < 2; a++)
        #pragma unroll
        for (int b = 0; b < 4; b++)
            #pragma unroll
            for (int c = 0; c < 4; c++) acc[a][b][c] = 0.f;

    unsigned abase0 = (unsigned)__cvta_generic_to_shared(Ah[0]);
    unsigned wbase0 = (unsigned)__cvta_generic_to_shared(Wh[0]);
    int a_row = lane & 15, a_col = (lane >> 4) * 8;
    int b_row = ((lane >> 4) * 8) + (lane & 7);
    int b_col = ((lane >> 3) & 1) * 8;

    int ar[2], ac[2];
    #pragma unroll
    for (int it = 0; it < 2; it++) {
        int i = tid + it * 256;
        ar[it] = i >> 2; ac[it] = (i & 3) << 3;
    }
    int wr = tid >> 2, wc = (tid & 3) << 3;

    #pragma unroll
    for (int it = 0; it < 2; it++)
        cpa16(abase0 + (ar[it] * 40 + ac[it]) * 2,
              g_oinh + (size_t)(m0 + ar[it]) * 256 + ac[it]);
    cpa16(wbase0 + (wr * 40 + wc) * 2, g_owh + (size_t)(n0 + wr) * 256 + wc);
    asm volatile("cp.async.commit_group;");

    for (int ki = 0; ki < 8; ++ki) {
        int buf = ki & 1;
        asm volatile("cp.async.wait_group 0;");
        __syncthreads();
        if (ki < 7) {
            int k1 = (ki + 1) * 32;
            unsigned ab = abase0 + (buf ^ 1) * 128 * 40 * 2;
            unsigned wb = wbase0 + (buf ^ 1) * 64 * 40 * 2;
            #pragma unroll
            for (int it = 0; it < 2; it++)
                cpa16(ab + (ar[it] * 40 + ac[it]) * 2,
                      g_oinh + (size_t)(m0 + ar[it]) * 256 + k1 + ac[it]);
            cpa16(wb + (wr * 40 + wc) * 2,
                  g_owh + (size_t)(n0 + wr) * 256 + k1 + wc);
            asm volatile("cp.async.commit_group;");
        }
        unsigned abase = abase0 + buf * 128 * 40 * 2;
        unsigned wbase = wbase0 + buf * 64 * 40 * 2;
        #pragma unroll
        for (int kc = 0; kc < 32; kc += 16) {
            unsigned af[2][4];
            ldsm4(af[0], abase + ((wm * 32 + a_row) * 40 + kc + a_col) * 2);
            ldsm4(af[1], abase + ((wm * 32 + 16 + a_row) * 40 + kc + a_col) * 2);
            #pragma unroll
            for (int n16 = 0; n16 < 2; n16++) {
                unsigned bf[4];
                ldsm4(bf, wbase + ((wn * 32 + n16 * 16 + b_row) * 40 + kc + b_col) * 2);
                mma16(acc[0][n16 * 2],     af[0], bf[0], bf[1]);
                mma16(acc[0][n16 * 2 + 1], af[0], bf[2], bf[3]);
                mma16(acc[1][n16 * 2],     af[1], bf[0], bf[1]);
                mma16(acc[1][n16 * 2 + 1], af[1], bf[2], bf[3]);
            }
        }
    }
    int gid = lane >> 2, tig = lane & 3;
    #pragma unroll
    for (int mm = 0; mm < 2; mm++) {
        #pragma unroll
        for (int nm = 0; nm < 4; nm++) {
            int r = m0 + wm * 32 + mm * 16 + gid;
            int c = n0 + wn * 32 + nm * 8 + 2 * tig;
            float2 xr0 = *(const float2*)&x[(size_t)r * D_DIM + c];
            float2 xr1 = *(const float2*)&x[(size_t)(r + 8) * D_DIM + c];
            float b0 = bias[c], b1 = bias[c + 1];
            *(float2*)&out[(size_t)r * D_DIM + c] =
                make_float2(acc[mm][nm][0] + b0 + xr0.x, acc[mm][nm][1] + b1 + xr0.y);
            *(float2*)&out[(size_t)(r + 8) * D_DIM + c] =
                make_float2(acc[mm][nm][2] + b0 + xr1.x, acc[mm][nm][3] + b1 + xr1.y);
        }
    }
}

// ---------------------------------------------------------------------------
// Launcher
// ---------------------------------------------------------------------------
extern "C" void kernel_launch(void* const* d_in, const int* in_sizes, int n_in,
                              void* d_out, int out_size) {
    const float* x    = (const float*)d_in[0];
    const float* uvqk = (const float*)d_in[1];
    const float* o_w  = (const float*)d_in[2];
    const float* o_b  = (const float*)d_in[3];
    const float* ts_w = (const float*)d_in[4];
    const int*   ts   = (const int*)d_in[5];
    float* out = (float*)d_out;

    ln_conv_kernel<<<1440, 256>>>(x, uvqk, o_w);
    gemm_uvqk_h<<<dim3(HID / 64, T_TOK / 128), 256>>>();
    attn_mma<<<dim3(100, 4), 256>>>(ts, ts_w);
    oin_kernel<<<T_TOK / 8, 256>>>();
    gemm_out_h<<<dim3(D_DIM / 64, T_TOK / 128), 256>>>(o_b, x, out);
}